// round 13
// baseline (speedup 1.0000x reference)
#include <cuda_runtime.h>
#include <math.h>

// ---------------------------------------------------------------------------
// maps[b] = bilin_up(out0,64)+bilin_up(out1,32)+bilin_up(out2,16) -> 256x256
// scores[b] = max( reflect-pad 5x5 gaussian blur of maps[b] )
// d_out = [256 scores][256*256*256 maps] fp32.
//
// 2048 blocks = (batch, 32-row strip), 128 threads = column pairs (finer
// granularity than R12's 64-row strips -> less wave-quantization skew).
// Packed-f32x2 fy tracking with ONE merged wrap branch per row, x-lerp
// brackets recomputed only inside the wrap, guard row per staged scale,
// single-slot FSEL halo store, 8-row mbuf ring, register-ring v-blur.
// Fused per-batch max via encoded atomicMax + arrival counter (8/batch).
// ---------------------------------------------------------------------------

typedef unsigned long long ull;

#define W0 0.18762723f
#define W1 0.20606817f
#define W2 0.21260941f

__device__ __forceinline__ ull pk2(float a, float b) {
    ull r; asm("mov.b64 %0, {%1,%2};" : "=l"(r) : "f"(a), "f"(b)); return r;
}
__device__ __forceinline__ float2 up2(ull v) {
    float2 r; asm("mov.b64 {%0,%1}, %2;" : "=f"(r.x), "=f"(r.y) : "l"(v)); return r;
}
__device__ __forceinline__ ull f2add(ull a, ull b) {
    ull r; asm("add.rn.f32x2 %0,%1,%2;" : "=l"(r) : "l"(a), "l"(b)); return r;
}
__device__ __forceinline__ ull f2mul(ull a, ull b) {
    ull r; asm("mul.rn.f32x2 %0,%1,%2;" : "=l"(r) : "l"(a), "l"(b)); return r;
}
__device__ __forceinline__ ull f2fma(ull a, ull b, ull c) {
    ull r; asm("fma.rn.f32x2 %0,%1,%2,%3;" : "=l"(r) : "l"(a), "l"(b), "l"(c)); return r;
}

__device__ __forceinline__ unsigned enc_f(float f) {
    unsigned u = __float_as_uint(f);
    return (u & 0x80000000u) ? ~u : (u | 0x80000000u);
}
__device__ __forceinline__ float dec_f(unsigned u) {
    return (u & 0x80000000u) ? __uint_as_float(u & 0x7fffffffu)
                             : __uint_as_float(~u);
}

__device__ unsigned g_enc[256];   // zero-init; reset by last block each call
__device__ unsigned g_cnt[256];   // zero-init; reset by last block each call

// x-lerp of this thread's column pair from a staged source row
template<int H>
__device__ __forceinline__ float2 xlerp(const float* row, int tid) {
    int n0 = 2 * tid * (H - 1), n1 = n0 + (H - 1);
    int xa = n0 / 255, xb = n1 / 255;
    float fxa = (float)(n0 - 255 * xa) * (1.0f / 255.0f);
    float fxb = (float)(n1 - 255 * xb) * (1.0f / 255.0f);
    int xa1 = min(xa + 1, H - 1), xb1 = min(xb + 1, H - 1);
    float A = row[xa], B = row[xa1], C = row[xb], D = row[xb1];
    return make_float2(fmaf(fxa, B - A, A), fmaf(fxb, D - C, C));
}

template<int H>
struct SC {
    int rowoff;          // smem offset of source row y0
    ull fy2;             // packed (fy, fy)
    ull xlo2, xdf2;      // packed x-lerp at y0, packed (hi - lo)
};

template<int H>
__device__ __forceinline__ void sc_init(SC<H>& s, const float* sm, int y, int rlo, int tid) {
    int num = y * (H - 1);
    int y0 = num / 255;
    float fy = (float)(num - 255 * y0) * (1.0f / 255.0f);
    s.fy2 = pk2(fy, fy);
    s.rowoff = (y0 - rlo) * H;
    float2 lo = xlerp<H>(sm + s.rowoff, tid);
    float2 hi = xlerp<H>(sm + s.rowoff + H, tid);   // guard row keeps this defined
    s.xlo2 = pk2(lo.x, lo.y);
    s.xdf2 = pk2(hi.x - lo.x, hi.y - lo.y);
}

template<int H>
__device__ __forceinline__ ull sc_m(const SC<H>& s) {
    return f2fma(s.fy2, s.xdf2, s.xlo2);
}

template<int H>
__device__ __forceinline__ void sc_wrap(SC<H>& s, const float* sm, ull m1_2, int tid) {
    s.fy2 = f2add(s.fy2, m1_2);
    s.rowoff += H;
    s.xlo2 = f2add(s.xlo2, s.xdf2);            // new lo = old hi
    float2 hi = xlerp<H>(sm + s.rowoff + H, tid);
    float2 lo = up2(s.xlo2);
    s.xdf2 = pk2(hi.x - lo.x, hi.y - lo.y);
}

// packed 5-tap horizontal blur; row = &mbuf[r][2*tid] (8B aligned)
__device__ __forceinline__ ull hblur(const float* row, ull w0p, ull w1p, ull w2p) {
    ull p0 = *(const ull*)&row[0];   // (m-2, m-1)
    ull p2 = *(const ull*)&row[2];   // (m0,  m1)
    ull p4 = *(const ull*)&row[4];   // (m2,  m3)
    float2 a = up2(p0), b = up2(p2), c = up2(p4);
    ull p1 = pk2(a.y, b.x);
    ull p3 = pk2(b.y, c.x);
    return f2fma(w0p, f2add(p0, p4), f2fma(w1p, f2add(p1, p3), f2mul(w2p, p2)));
}

__global__ void __launch_bounds__(128, 7)
fused_strip(const float* __restrict__ in0,
            const float* __restrict__ in1,
            const float* __restrict__ in2,
            float* __restrict__ maps,
            float* __restrict__ scores) {
    __shared__ __align__(16) float s0[12 * 64];   // staged + guard row
    __shared__ __align__(16) float s1[8 * 32];
    __shared__ __align__(16) float s2[6 * 16];
    __shared__ __align__(16) float mbuf[8][264];  // [0..259] used, pad 260..263
    __shared__ float wred[4];

    const int tid = threadIdx.x;
    const int bx  = blockIdx.x;
    const int b   = bx >> 3;
    const int q   = bx & 7;
    const int Y0  = q << 5;

    const int amin = max(0, Y0 - 2);
    const int amax = min(255, Y0 + 33);
    const int rlo0 = (amin * 63) / 255;
    const int rlo1 = (amin * 31) / 255;
    const int rlo2 = (amin * 15) / 255;
    const int rhi0 = min((amax * 63) / 255 + 1, 63);
    const int rhi1 = min((amax * 31) / 255 + 1, 31);
    const int rhi2 = min((amax * 15) / 255 + 1, 15);

    // stage sources (coalesced float4) + guard row (duplicate of last row)
    {
        const float* gb = in0 + (size_t)b * 4096 + rlo0 * 64;
        int n = (rhi0 - rlo0 + 1) * 16;
        for (int i = tid; i < n; i += 128) ((float4*)s0)[i] = ((const float4*)gb)[i];
        const float* gr = in0 + (size_t)b * 4096 + rhi0 * 64;
        if (tid < 64) s0[n * 4 + tid] = gr[tid];
    }
    {
        const float* gb = in1 + (size_t)b * 1024 + rlo1 * 32;
        int n = (rhi1 - rlo1 + 1) * 8;
        for (int i = tid; i < n; i += 128) ((float4*)s1)[i] = ((const float4*)gb)[i];
        const float* gr = in1 + (size_t)b * 1024 + rhi1 * 32;
        if (tid < 32) s1[n * 4 + tid] = gr[tid];
    }
    {
        const float* gb = in2 + (size_t)b * 256 + rlo2 * 16;
        int n = (rhi2 - rlo2 + 1) * 4;
        for (int i = tid; i < n; i += 128) ((float4*)s2)[i] = ((const float4*)gb)[i];
        const float* gr = in2 + (size_t)b * 256 + rhi2 * 16;
        if (tid < 16) s2[n * 4 + tid] = gr[tid];
    }

    // per-thread halo-store slot: threads 0/1/126/127 fill reflect cells,
    // everyone else hits the dummy pad (same-address stores collapse).
    int hoff; bool pickY;
    if (tid == 1)        { hoff = 0;   pickY = false; }
    else if (tid == 0)   { hoff = 1;   pickY = true;  }
    else if (tid == 127) { hoff = 258; pickY = false; }
    else if (tid == 126) { hoff = 259; pickY = true;  }
    else                 { hoff = 260; pickY = false; }

    const ull w0p = pk2(W0, W0), w1p = pk2(W1, W1), w2p = pk2(W2, W2);
    const ull incA = pk2(63.0f / 255.0f, 63.0f / 255.0f);
    const ull incB = pk2(31.0f / 255.0f, 31.0f / 255.0f);
    const ull incC = pk2(15.0f / 255.0f, 15.0f / 255.0f);
    const ull m1_2 = pk2(-1.0f, -1.0f);

    SC<64> cA; SC<32> cB; SC<16> cC;

    __syncthreads();

// merged advance: ONE uniform branch per row for all 3 scales
#define ADV_ALL                                                          \
    {                                                                    \
        cA.fy2 = f2add(cA.fy2, incA);                                    \
        cB.fy2 = f2add(cB.fy2, incB);                                    \
        cC.fy2 = f2add(cC.fy2, incC);                                    \
        bool wA = up2(cA.fy2).x >= 1.0f;                                 \
        bool wB = up2(cB.fy2).x >= 1.0f;                                 \
        bool wC = up2(cC.fy2).x >= 1.0f;                                 \
        if (wA | wB | wC) {                                              \
            if (wA) sc_wrap(cA, s0, m1_2, tid);                          \
            if (wB) sc_wrap(cB, s1, m1_2, tid);                          \
            if (wC) sc_wrap(cC, s2, m1_2, tid);                          \
        }                                                                \
    }

    // ---- prime rows h(Y0-2), h(Y0-1) (reflect at top edge) ----
    {
        int p0 = (q == 0) ? 2 : Y0 - 2;
        int p1 = (q == 0) ? 1 : Y0 - 1;
        sc_init(cA, s0, p0, rlo0, tid);
        sc_init(cB, s1, p0, rlo1, tid);
        sc_init(cC, s2, p0, rlo2, tid);
        ull m2 = f2add(f2add(sc_m(cA), sc_m(cB)), sc_m(cC));
        *(ull*)&mbuf[0][2 + 2 * tid] = m2;
        float2 mv = up2(m2);
        mbuf[0][hoff] = pickY ? mv.y : mv.x;
        sc_init(cA, s0, p1, rlo0, tid);
        sc_init(cB, s1, p1, rlo1, tid);
        sc_init(cC, s2, p1, rlo2, tid);
        m2 = f2add(f2add(sc_m(cA), sc_m(cB)), sc_m(cC));
        *(ull*)&mbuf[1][2 + 2 * tid] = m2;
        mv = up2(m2);
        mbuf[1][hoff] = pickY ? mv.y : mv.x;
    }
    __syncthreads();
    ull ha = 0, hb = 0;
    ull hc = hblur(&mbuf[0][2 * tid], w0p, w1p, w2p);
    ull hd = hblur(&mbuf[1][2 * tid], w0p, w1p, w2p);
    __syncthreads();

    // ---- main strip: 4 phases x 8 rows ----
    sc_init(cA, s0, Y0, rlo0, tid);
    sc_init(cB, s1, Y0, rlo1, tid);
    sc_init(cC, s2, Y0, rlo2, tid);

    float* mp = maps + (size_t)b * 65536 + (size_t)Y0 * 256 + 2 * tid;
    float lmax = -INFINITY;

    // peeled phase 0 (max-guard only here)
    {
        #pragma unroll
        for (int r = 0; r < 8; ++r) {
            ull m2 = f2add(f2add(sc_m(cA), sc_m(cB)), sc_m(cC));
            *(ull*)&mbuf[r][2 + 2 * tid] = m2;
            float2 mv = up2(m2);
            mbuf[r][hoff] = pickY ? mv.y : mv.x;
            *(ull*)(mp + r * 256) = m2;
            ADV_ALL
        }
        mp += 2048;
        __syncthreads();
        #pragma unroll
        for (int r = 0; r < 8; ++r) {
            ull he = hblur(&mbuf[r][2 * tid], w0p, w1p, w2p);
            ull vv = f2fma(w0p, f2add(ha, he),
                     f2fma(w1p, f2add(hb, hd), f2mul(w2p, hc)));
            if (r >= 2) {
                float2 vf = up2(vv);
                lmax = fmaxf(lmax, fmaxf(vf.x, vf.y));
            }
            ha = hb; hb = hc; hc = hd; hd = he;
        }
        __syncthreads();
    }

    #pragma unroll 1
    for (int p = 1; p < 4; ++p) {
        #pragma unroll
        for (int r = 0; r < 8; ++r) {
            ull m2 = f2add(f2add(sc_m(cA), sc_m(cB)), sc_m(cC));
            *(ull*)&mbuf[r][2 + 2 * tid] = m2;
            float2 mv = up2(m2);
            mbuf[r][hoff] = pickY ? mv.y : mv.x;
            *(ull*)(mp + r * 256) = m2;
            ADV_ALL
        }
        mp += 2048;
        __syncthreads();
        #pragma unroll
        for (int r = 0; r < 8; ++r) {
            ull he = hblur(&mbuf[r][2 * tid], w0p, w1p, w2p);
            ull vv = f2fma(w0p, f2add(ha, he),
                     f2fma(w1p, f2add(hb, hd), f2mul(w2p, hc)));
            float2 vf = up2(vv);
            lmax = fmaxf(lmax, fmaxf(vf.x, vf.y));
            ha = hb; hb = hc; hc = hd; hd = he;
        }
        __syncthreads();
    }

    if (q < 7) {
        // rows Y0+32, Y0+33 finish v rows Y0+30, Y0+31 (no maps store)
        #pragma unroll
        for (int e = 0; e < 2; ++e) {
            ull m2 = f2add(f2add(sc_m(cA), sc_m(cB)), sc_m(cC));
            *(ull*)&mbuf[e][2 + 2 * tid] = m2;
            float2 mv = up2(m2);
            mbuf[e][hoff] = pickY ? mv.y : mv.x;
            ADV_ALL
        }
        __syncthreads();
        #pragma unroll
        for (int e = 0; e < 2; ++e) {
            ull he = hblur(&mbuf[e][2 * tid], w0p, w1p, w2p);
            ull vv = f2fma(w0p, f2add(ha, he),
                     f2fma(w1p, f2add(hb, hd), f2mul(w2p, hc)));
            float2 vf = up2(vv);
            lmax = fmaxf(lmax, fmaxf(vf.x, vf.y));
            ha = hb; hb = hc; hc = hd; hd = he;
        }
    } else {
        // ring holds h252..h255; reflect rows 256->254, 257->253
        ull v254 = f2fma(w0p, f2add(ha, hc), f2fma(w1p, f2add(hb, hd), f2mul(w2p, hc)));
        ull v255 = f2fma(w0p, f2add(hb, hb), f2fma(w1p, f2add(hc, hc), f2mul(w2p, hd)));
        float2 a4 = up2(v254), a5 = up2(v255);
        lmax = fmaxf(lmax, fmaxf(fmaxf(a4.x, a4.y), fmaxf(a5.x, a5.y)));
    }

    // block max -> fused per-batch reduction (max is order-independent;
    // last-arriving block decodes and resets scratch for graph replay)
    #pragma unroll
    for (int off = 16; off; off >>= 1)
        lmax = fmaxf(lmax, __shfl_xor_sync(0xFFFFFFFFu, lmax, off));
    if ((tid & 31) == 0) wred[tid >> 5] = lmax;
    __syncthreads();
    if (tid == 0) {
        float m = fmaxf(fmaxf(wred[0], wred[1]), fmaxf(wred[2], wred[3]));
        atomicMax(&g_enc[b], enc_f(m));
        __threadfence();
        unsigned t = atomicAdd(&g_cnt[b], 1u);
        if (t == 7u) {
            unsigned e = atomicExch(&g_enc[b], 0u);
            scores[b] = dec_f(e);
            atomicExch(&g_cnt[b], 0u);
        }
    }
}

extern "C" void kernel_launch(void* const* d_in, const int* in_sizes, int n_in,
                              void* d_out, int out_size) {
    const float* out0 = (const float*)d_in[0];  // [256,64,64]
    const float* out1 = (const float*)d_in[1];  // [256,32,32]
    const float* out2 = (const float*)d_in[2];  // [256,16,16]
    float* out = (float*)d_out;

    fused_strip<<<2048, 128>>>(out0, out1, out2, out + 256, out);
}

// round 14
// speedup vs baseline: 1.0922x; 1.0922x over previous
#include <cuda_runtime.h>
#include <math.h>

// ---------------------------------------------------------------------------
// maps[b] = bilin_up(out0,64)+bilin_up(out1,32)+bilin_up(out2,16) -> 256x256
// scores[b] = max( reflect-pad 5x5 gaussian blur of maps[b] )
// d_out = [256 scores][256*256*256 maps] fp32.
//
// 1024 blocks = (batch, 64-row quarter strip), 128 threads = column pairs.
// R12 structure + SUMXL: the three per-scale x-lerp base values are kept
// pre-summed in one packed register (updated only in the rare merged wrap
// branch), so each row's m is 3 chained fma.f32x2. Packed fy tracking,
// guard row per staged scale, single-slot FSEL halo store, 8-row mbuf ring,
// register-ring v-blur. Fused per-batch max via encoded atomicMax + counter.
// ---------------------------------------------------------------------------

typedef unsigned long long ull;

#define W0 0.18762723f
#define W1 0.20606817f
#define W2 0.21260941f

__device__ __forceinline__ ull pk2(float a, float b) {
    ull r; asm("mov.b64 %0, {%1,%2};" : "=l"(r) : "f"(a), "f"(b)); return r;
}
__device__ __forceinline__ float2 up2(ull v) {
    float2 r; asm("mov.b64 {%0,%1}, %2;" : "=f"(r.x), "=f"(r.y) : "l"(v)); return r;
}
__device__ __forceinline__ ull f2add(ull a, ull b) {
    ull r; asm("add.rn.f32x2 %0,%1,%2;" : "=l"(r) : "l"(a), "l"(b)); return r;
}
__device__ __forceinline__ ull f2mul(ull a, ull b) {
    ull r; asm("mul.rn.f32x2 %0,%1,%2;" : "=l"(r) : "l"(a), "l"(b)); return r;
}
__device__ __forceinline__ ull f2fma(ull a, ull b, ull c) {
    ull r; asm("fma.rn.f32x2 %0,%1,%2,%3;" : "=l"(r) : "l"(a), "l"(b), "l"(c)); return r;
}

__device__ __forceinline__ unsigned enc_f(float f) {
    unsigned u = __float_as_uint(f);
    return (u & 0x80000000u) ? ~u : (u | 0x80000000u);
}
__device__ __forceinline__ float dec_f(unsigned u) {
    return (u & 0x80000000u) ? __uint_as_float(u & 0x7fffffffu)
                             : __uint_as_float(~u);
}

__device__ unsigned g_enc[256];   // zero-init; reset by last block each call
__device__ unsigned g_cnt[256];   // zero-init; reset by last block each call

// x-lerp of this thread's column pair from a staged source row
template<int H>
__device__ __forceinline__ float2 xlerp(const float* row, int tid) {
    int n0 = 2 * tid * (H - 1), n1 = n0 + (H - 1);
    int xa = n0 / 255, xb = n1 / 255;
    float fxa = (float)(n0 - 255 * xa) * (1.0f / 255.0f);
    float fxb = (float)(n1 - 255 * xb) * (1.0f / 255.0f);
    int xa1 = min(xa + 1, H - 1), xb1 = min(xb + 1, H - 1);
    float A = row[xa], B = row[xa1], C = row[xb], D = row[xb1];
    return make_float2(fmaf(fxa, B - A, A), fmaf(fxb, D - C, C));
}

template<int H>
struct SC {
    int rowoff;          // smem offset of source row y0
    ull fy2;             // packed (fy, fy)
    ull xhi2, xdf2;      // packed x-lerp at y0+1, packed (hi - lo)
};

// init: fills cache, returns packed lo (for SUMXL accumulation)
template<int H>
__device__ __forceinline__ ull sc_init(SC<H>& s, const float* sm, int y, int rlo, int tid) {
    int num = y * (H - 1);
    int y0 = num / 255;
    float fy = (float)(num - 255 * y0) * (1.0f / 255.0f);
    s.fy2 = pk2(fy, fy);
    s.rowoff = (y0 - rlo) * H;
    float2 lo = xlerp<H>(sm + s.rowoff, tid);
    float2 hi = xlerp<H>(sm + s.rowoff + H, tid);   // guard row keeps this defined
    s.xhi2 = pk2(hi.x, hi.y);
    s.xdf2 = pk2(hi.x - lo.x, hi.y - lo.y);
    return pk2(lo.x, lo.y);
}

// wrap: lo_new = hi_old (SUMXL += xd_old done by caller), hi_new gathered
template<int H>
__device__ __forceinline__ void sc_wrap(SC<H>& s, const float* sm, ull m1_2, int tid) {
    s.fy2 = f2add(s.fy2, m1_2);
    s.rowoff += H;
    float2 hi = xlerp<H>(sm + s.rowoff + H, tid);
    ull hi2 = pk2(hi.x, hi.y);
    float2 lo = up2(s.xhi2);                    // old hi = new lo
    s.xdf2 = pk2(hi.x - lo.x, hi.y - lo.y);
    s.xhi2 = hi2;
}

// packed 5-tap horizontal blur; row = &mbuf[r][2*tid] (8B aligned)
__device__ __forceinline__ ull hblur(const float* row, ull w0p, ull w1p, ull w2p) {
    ull p0 = *(const ull*)&row[0];   // (m-2, m-1)
    ull p2 = *(const ull*)&row[2];   // (m0,  m1)
    ull p4 = *(const ull*)&row[4];   // (m2,  m3)
    float2 a = up2(p0), b = up2(p2), c = up2(p4);
    ull p1 = pk2(a.y, b.x);
    ull p3 = pk2(b.y, c.x);
    return f2fma(w0p, f2add(p0, p4), f2fma(w1p, f2add(p1, p3), f2mul(w2p, p2)));
}

__global__ void __launch_bounds__(128, 7)
fused_quarter(const float* __restrict__ in0,
              const float* __restrict__ in1,
              const float* __restrict__ in2,
              float* __restrict__ maps,
              float* __restrict__ scores) {
    __shared__ __align__(16) float s0[20 * 64];   // staged + guard row
    __shared__ __align__(16) float s1[12 * 32];
    __shared__ __align__(16) float s2[8 * 16];
    __shared__ __align__(16) float mbuf[8][264];  // [0..259] used, pad 260..263
    __shared__ float wred[4];

    const int tid = threadIdx.x;
    const int bx  = blockIdx.x;
    const int b   = bx >> 2;
    const int q   = bx & 3;
    const int yq0 = q * 64;

    const int amin = max(0, yq0 - 2);
    const int amax = min(255, yq0 + 65);
    const int rlo0 = (amin * 63) / 255;
    const int rlo1 = (amin * 31) / 255;
    const int rlo2 = (amin * 15) / 255;
    const int rhi0 = min((amax * 63) / 255 + 1, 63);
    const int rhi1 = min((amax * 31) / 255 + 1, 31);
    const int rhi2 = min((amax * 15) / 255 + 1, 15);

    // stage sources (coalesced float4) + guard row (duplicate of last row)
    {
        const float* gb = in0 + (size_t)b * 4096 + rlo0 * 64;
        int n = (rhi0 - rlo0 + 1) * 16;
        for (int i = tid; i < n; i += 128) ((float4*)s0)[i] = ((const float4*)gb)[i];
        const float* gr = in0 + (size_t)b * 4096 + rhi0 * 64;
        if (tid < 64) s0[n * 4 + tid] = gr[tid];
    }
    {
        const float* gb = in1 + (size_t)b * 1024 + rlo1 * 32;
        int n = (rhi1 - rlo1 + 1) * 8;
        for (int i = tid; i < n; i += 128) ((float4*)s1)[i] = ((const float4*)gb)[i];
        const float* gr = in1 + (size_t)b * 1024 + rhi1 * 32;
        if (tid < 32) s1[n * 4 + tid] = gr[tid];
    }
    {
        const float* gb = in2 + (size_t)b * 256 + rlo2 * 16;
        int n = (rhi2 - rlo2 + 1) * 4;
        for (int i = tid; i < n; i += 128) ((float4*)s2)[i] = ((const float4*)gb)[i];
        const float* gr = in2 + (size_t)b * 256 + rhi2 * 16;
        if (tid < 16) s2[n * 4 + tid] = gr[tid];
    }

    // per-thread halo-store slot: threads 0/1/126/127 fill reflect cells,
    // everyone else hits the dummy pad (same-address stores collapse).
    int hoff; bool pickY;
    if (tid == 1)        { hoff = 0;   pickY = false; }
    else if (tid == 0)   { hoff = 1;   pickY = true;  }
    else if (tid == 127) { hoff = 258; pickY = false; }
    else if (tid == 126) { hoff = 259; pickY = true;  }
    else                 { hoff = 260; pickY = false; }

    const ull w0p = pk2(W0, W0), w1p = pk2(W1, W1), w2p = pk2(W2, W2);
    const ull incA = pk2(63.0f / 255.0f, 63.0f / 255.0f);
    const ull incB = pk2(31.0f / 255.0f, 31.0f / 255.0f);
    const ull incC = pk2(15.0f / 255.0f, 15.0f / 255.0f);
    const ull m1_2 = pk2(-1.0f, -1.0f);

    SC<64> cA; SC<32> cB; SC<16> cC;
    ull sumxl;

    __syncthreads();

// row m value from caches: 3 chained packed FMAs onto the pre-summed lo
#define M_ROW  f2fma(cA.fy2, cA.xdf2,                                   \
               f2fma(cB.fy2, cB.xdf2,                                   \
               f2fma(cC.fy2, cC.xdf2, sumxl)))

// merged advance: ONE uniform branch per row for all 3 scales
#define ADV_ALL                                                          \
    {                                                                    \
        cA.fy2 = f2add(cA.fy2, incA);                                    \
        cB.fy2 = f2add(cB.fy2, incB);                                    \
        cC.fy2 = f2add(cC.fy2, incC);                                    \
        bool wA = up2(cA.fy2).x >= 1.0f;                                 \
        bool wB = up2(cB.fy2).x >= 1.0f;                                 \
        bool wC = up2(cC.fy2).x >= 1.0f;                                 \
        if (wA | wB | wC) {                                              \
            if (wA) { sumxl = f2add(sumxl, cA.xdf2); sc_wrap(cA, s0, m1_2, tid); } \
            if (wB) { sumxl = f2add(sumxl, cB.xdf2); sc_wrap(cB, s1, m1_2, tid); } \
            if (wC) { sumxl = f2add(sumxl, cC.xdf2); sc_wrap(cC, s2, m1_2, tid); } \
        }                                                                \
    }

#define INIT_ALL(Y)                                                      \
    {                                                                    \
        ull loA = sc_init(cA, s0, (Y), rlo0, tid);                       \
        ull loB = sc_init(cB, s1, (Y), rlo1, tid);                       \
        ull loC = sc_init(cC, s2, (Y), rlo2, tid);                       \
        sumxl = f2add(f2add(loA, loB), loC);                             \
    }

    // ---- prime rows h(yq0-2), h(yq0-1) (reflect at top edge) ----
    {
        int p0 = (q == 0) ? 2 : yq0 - 2;
        int p1 = (q == 0) ? 1 : yq0 - 1;
        INIT_ALL(p0)
        ull m2 = M_ROW;
        *(ull*)&mbuf[0][2 + 2 * tid] = m2;
        float2 mv = up2(m2);
        mbuf[0][hoff] = pickY ? mv.y : mv.x;
        INIT_ALL(p1)
        m2 = M_ROW;
        *(ull*)&mbuf[1][2 + 2 * tid] = m2;
        mv = up2(m2);
        mbuf[1][hoff] = pickY ? mv.y : mv.x;
    }
    __syncthreads();
    ull ha = 0, hb = 0;
    ull hc = hblur(&mbuf[0][2 * tid], w0p, w1p, w2p);
    ull hd = hblur(&mbuf[1][2 * tid], w0p, w1p, w2p);
    __syncthreads();

    // ---- main strip: 8 phases x 8 rows ----
    INIT_ALL(yq0)

    float* mp = maps + (size_t)b * 65536 + (size_t)yq0 * 256 + 2 * tid;
    float lmax = -INFINITY;

    // peeled phase 0 (max-guard only here)
    {
        #pragma unroll
        for (int r = 0; r < 8; ++r) {
            ull m2 = M_ROW;
            *(ull*)&mbuf[r][2 + 2 * tid] = m2;
            float2 mv = up2(m2);
            mbuf[r][hoff] = pickY ? mv.y : mv.x;
            *(ull*)(mp + r * 256) = m2;
            ADV_ALL
        }
        mp += 2048;
        __syncthreads();
        #pragma unroll
        for (int r = 0; r < 8; ++r) {
            ull he = hblur(&mbuf[r][2 * tid], w0p, w1p, w2p);
            ull vv = f2fma(w0p, f2add(ha, he),
                     f2fma(w1p, f2add(hb, hd), f2mul(w2p, hc)));
            if (r >= 2) {
                float2 vf = up2(vv);
                lmax = fmaxf(lmax, fmaxf(vf.x, vf.y));
            }
            ha = hb; hb = hc; hc = hd; hd = he;
        }
        __syncthreads();
    }

    #pragma unroll 1
    for (int p = 1; p < 8; ++p) {
        #pragma unroll
        for (int r = 0; r < 8; ++r) {
            ull m2 = M_ROW;
            *(ull*)&mbuf[r][2 + 2 * tid] = m2;
            float2 mv = up2(m2);
            mbuf[r][hoff] = pickY ? mv.y : mv.x;
            *(ull*)(mp + r * 256) = m2;
            ADV_ALL
        }
        mp += 2048;
        __syncthreads();
        #pragma unroll
        for (int r = 0; r < 8; ++r) {
            ull he = hblur(&mbuf[r][2 * tid], w0p, w1p, w2p);
            ull vv = f2fma(w0p, f2add(ha, he),
                     f2fma(w1p, f2add(hb, hd), f2mul(w2p, hc)));
            float2 vf = up2(vv);
            lmax = fmaxf(lmax, fmaxf(vf.x, vf.y));
            ha = hb; hb = hc; hc = hd; hd = he;
        }
        __syncthreads();
    }

    if (q < 3) {
        // rows yq0+64, yq0+65 finish v rows yq0+62, yq0+63 (no maps store)
        #pragma unroll
        for (int e = 0; e < 2; ++e) {
            ull m2 = M_ROW;
            *(ull*)&mbuf[e][2 + 2 * tid] = m2;
            float2 mv = up2(m2);
            mbuf[e][hoff] = pickY ? mv.y : mv.x;
            ADV_ALL
        }
        __syncthreads();
        #pragma unroll
        for (int e = 0; e < 2; ++e) {
            ull he = hblur(&mbuf[e][2 * tid], w0p, w1p, w2p);
            ull vv = f2fma(w0p, f2add(ha, he),
                     f2fma(w1p, f2add(hb, hd), f2mul(w2p, hc)));
            float2 vf = up2(vv);
            lmax = fmaxf(lmax, fmaxf(vf.x, vf.y));
            ha = hb; hb = hc; hc = hd; hd = he;
        }
    } else {
        // ring holds h252..h255; reflect rows 256->254, 257->253
        ull v254 = f2fma(w0p, f2add(ha, hc), f2fma(w1p, f2add(hb, hd), f2mul(w2p, hc)));
        ull v255 = f2fma(w0p, f2add(hb, hb), f2fma(w1p, f2add(hc, hc), f2mul(w2p, hd)));
        float2 a4 = up2(v254), a5 = up2(v255);
        lmax = fmaxf(lmax, fmaxf(fmaxf(a4.x, a4.y), fmaxf(a5.x, a5.y)));
    }

    // block max -> fused per-batch reduction (max is order-independent;
    // last-arriving block decodes and resets scratch for graph replay)
    #pragma unroll
    for (int off = 16; off; off >>= 1)
        lmax = fmaxf(lmax, __shfl_xor_sync(0xFFFFFFFFu, lmax, off));
    if ((tid & 31) == 0) wred[tid >> 5] = lmax;
    __syncthreads();
    if (tid == 0) {
        float m = fmaxf(fmaxf(wred[0], wred[1]), fmaxf(wred[2], wred[3]));
        atomicMax(&g_enc[b], enc_f(m));
        __threadfence();
        unsigned t = atomicAdd(&g_cnt[b], 1u);
        if (t == 3u) {
            unsigned e = atomicExch(&g_enc[b], 0u);
            scores[b] = dec_f(e);
            atomicExch(&g_cnt[b], 0u);
        }
    }
}

extern "C" void kernel_launch(void* const* d_in, const int* in_sizes, int n_in,
                              void* d_out, int out_size) {
    const float* out0 = (const float*)d_in[0];  // [256,64,64]
    const float* out1 = (const float*)d_in[1];  // [256,32,32]
    const float* out2 = (const float*)d_in[2];  // [256,16,16]
    float* out = (float*)d_out;

    fused_quarter<<<1024, 128>>>(out0, out1, out2, out + 256, out);
}